// round 5
// baseline (speedup 1.0000x reference)
#include <cuda_runtime.h>
#include <cstdint>

// Problem constants
#define NPTS   131072
#define DIMK   64      // slice width (we use inpt[:, 64:128])
#define KCENT  1024
#define INROW  128     // inpt row stride

// Tiling
#define BM 64
#define BN 128
#define TM 8
#define TN 4
#define THREADS 256

__device__ float g_cnorm[KCENT];

// ---- f32x2 helpers (exact fp32 semantics, 2 FMAs per instruction) ----
__device__ __forceinline__ void fma2(unsigned long long& d,
                                     unsigned long long a,
                                     unsigned long long b) {
    asm("fma.rn.f32x2 %0, %1, %2, %0;" : "+l"(d) : "l"(a), "l"(b));
}
__device__ __forceinline__ float2 unpack2(unsigned long long v) {
    float2 f;
    asm("mov.b64 {%0, %1}, %2;" : "=f"(f.x), "=f"(f.y) : "l"(v));
    return f;
}
// 16-byte shared load producing two f32x2 operand registers (no extra MOVs in
// SASS: LDS.128 writes an aligned quad, mov.b64 is resolved by allocation)
__device__ __forceinline__ void lds128(unsigned addr,
                                       unsigned long long& lo,
                                       unsigned long long& hi) {
    asm volatile(
        "{\n\t"
        ".reg .b32 t0, t1, t2, t3;\n\t"
        "ld.shared.v4.b32 {t0, t1, t2, t3}, [%2];\n\t"
        "mov.b64 %0, {t0, t1};\n\t"
        "mov.b64 %1, {t2, t3};\n\t"
        "}"
        : "=l"(lo), "=l"(hi) : "r"(addr));
}

// ---- center squared norms ----
__global__ void cnorm_kernel(const float* __restrict__ centers) {
    int n = blockIdx.x * blockDim.x + threadIdx.x;
    if (n < KCENT) {
        const float* c = centers + (size_t)n * DIMK;
        float s = 0.f;
        #pragma unroll
        for (int k = 0; k < DIMK; k++) s = fmaf(c[k], c[k], s);
        g_cnorm[n] = s;
    }
}

// ---- fused GEMM + argmin ----
// Xs: [m][k]            64 x 64 floats (16 KB); a-reads are LDS.128 broadcast
// Cs: quad-interleaved  [k/4][n][4] = 16 x 128 x 4 floats (32 KB);
//     b-reads are LDS.128, 32 lanes x 16B = contiguous 512B (conflict-free)
__global__ __launch_bounds__(THREADS, 2)
void label_kernel(const float* __restrict__ inpt,
                  const float* __restrict__ centers,
                  float* __restrict__ out) {
    __shared__ __align__(16) float Xs[BM * DIMK];             // 4096 floats
    __shared__ __align__(16) float Cs[(DIMK / 4) * BN * 4];   // 8192 floats

    const int tid = threadIdx.x;
    const int ty  = tid >> 5;   // warp id 0..7  -> rows ty*8 .. ty*8+7
    const int tx  = tid & 31;   // lane          -> cols tx + 32*j
    const int m0  = blockIdx.x * BM;
    const int mbase = ty * TM;

    // Load X tile: rows m0..m0+63, cols 64..127 (second slice)
    {
        const int r  = tid >> 4;   // 0..15
        const int kg = tid & 15;   // float4 group within the 64 cols
        #pragma unroll
        for (int rep = 0; rep < 4; rep++) {
            const int m = r + rep * 16;
            float4 v = *reinterpret_cast<const float4*>(
                inpt + (size_t)(m0 + m) * INROW + DIMK + kg * 4);
            *reinterpret_cast<float4*>(&Xs[m * DIMK + kg * 4]) = v;
        }
    }

    const unsigned xs_base = (unsigned)__cvta_generic_to_shared(Xs);
    const unsigned cs_base = (unsigned)__cvta_generic_to_shared(Cs);

    float bestd[TM];
    int   bestn[TM];
    #pragma unroll
    for (int i = 0; i < TM; i++) {
        bestd[i] = __int_as_float(0x7f800000);  // +inf sentinel
        bestn[i] = 0;
    }

    for (int n0 = 0; n0 < KCENT; n0 += BN) {
        __syncthreads();
        // Load C tile, quad-interleaved on k: Cs[(k/4)*512 + n*4 .. +3]
        {
            const int n = tid >> 1;       // 0..127
            const int h = tid & 1;        // which 32-wide half of k
            const float* src = centers + (size_t)(n0 + n) * DIMK + h * 32;
            #pragma unroll
            for (int i4 = 0; i4 < 8; i4++) {
                float4 v = *reinterpret_cast<const float4*>(src + i4 * 4);
                const int k = h * 32 + i4 * 4;
                *reinterpret_cast<float4*>(&Cs[(k >> 2) * (BN * 4) + n * 4]) = v;
            }
        }
        __syncthreads();

        // acc[i][j] packs (sum over k%2==0, sum over k%2==1)
        unsigned long long acc[TM][TN];
        #pragma unroll
        for (int i = 0; i < TM; i++)
            #pragma unroll
            for (int j = 0; j < TN; j++) acc[i][j] = 0ull;

        #pragma unroll 1
        for (int kq = 0; kq < DIMK / 4; kq++) {   // 4 k-values per step
            unsigned long long b_lo[TN], b_hi[TN];
            #pragma unroll
            for (int j = 0; j < TN; j++)
                lds128(cs_base +
                       (unsigned)((kq * (BN * 4) + (tx + 32 * j) * 4) * 4),
                       b_lo[j], b_hi[j]);
            unsigned long long a_lo[TM], a_hi[TM];
            #pragma unroll
            for (int i = 0; i < TM; i++)
                lds128(xs_base +
                       (unsigned)(((mbase + i) * DIMK + kq * 4) * 4),
                       a_lo[i], a_hi[i]);
            #pragma unroll
            for (int i = 0; i < TM; i++)
                #pragma unroll
                for (int j = 0; j < TN; j++) {
                    fma2(acc[i][j], a_lo[i], b_lo[j]);
                    fma2(acc[i][j], a_hi[i], b_hi[j]);
                }
        }

        // Epilogue: d = ||c||^2 - 2*dot, running argmin (ascending n keeps
        // first-minimum semantics of jnp.argmin)
        float cn[TN];
        #pragma unroll
        for (int j = 0; j < TN; j++)
            cn[j] = __ldg(&g_cnorm[n0 + tx + 32 * j]);

        #pragma unroll
        for (int i = 0; i < TM; i++) {
            #pragma unroll
            for (int j = 0; j < TN; j++) {
                float2 s = unpack2(acc[i][j]);
                float dot = s.x + s.y;
                float d = fmaf(-2.0f, dot, cn[j]);
                int n = n0 + tx + 32 * j;
                if (d < bestd[i]) { bestd[i] = d; bestn[i] = n; }
            }
        }
    }

    // Warp reduction per row (lanes hold disjoint n-sets); tie -> lower index
    #pragma unroll
    for (int i = 0; i < TM; i++) {
        float d = bestd[i];
        int   n = bestn[i];
        #pragma unroll
        for (int off = 16; off > 0; off >>= 1) {
            float od = __shfl_down_sync(0xffffffffu, d, off);
            int   on = __shfl_down_sync(0xffffffffu, n, off);
            if (od < d || (od == d && on < n)) { d = od; n = on; }
        }
        // Output dtype is float32: labels 0..1023 are exactly representable.
        if (tx == 0) out[m0 + mbase + i] = (float)n;
    }
}

extern "C" void kernel_launch(void* const* d_in, const int* in_sizes, int n_in,
                              void* d_out, int out_size) {
    // Identify inputs by element count (robust to metadata ordering):
    //   inpt:     131072*128 = 16777216 elements (unique)
    //   centers0: 1024*64    = 65536 elements (first  such tensor)
    //   centers1: 1024*64    = 65536 elements (second such tensor)
    const float* inpt     = nullptr;
    const float* centers1 = nullptr;
    int centers_seen = 0;
    for (int i = 0; i < n_in; i++) {
        if (in_sizes[i] == NPTS * INROW) {
            inpt = (const float*)d_in[i];
        } else if (in_sizes[i] == KCENT * DIMK) {
            centers_seen++;
            if (centers_seen == 2) centers1 = (const float*)d_in[i];
        }
    }
    // Fallback to assumed order if sizes didn't disambiguate
    if (!inpt)     inpt     = (const float*)d_in[0];
    if (!centers1) centers1 = (const float*)d_in[n_in - 1];

    float* out = (float*)d_out;

    cnorm_kernel<<<(KCENT + 255) / 256, 256>>>(centers1);
    label_kernel<<<NPTS / BM, THREADS>>>(inpt, centers1, out);
}

// round 6
// speedup vs baseline: 1.1096x; 1.1096x over previous
#include <cuda_runtime.h>
#include <cstdint>

// Problem constants
#define NPTS   131072
#define DIMK   64      // slice width (we use inpt[:, 64:128])
#define KCENT  1024
#define INROW  128     // inpt row stride

// Tiling
#define BM 64
#define BN 128
#define TM 8
#define TN 4
#define THREADS 256

#define XS_FLOATS   (BM * DIMK)                 // 4096
#define CS_FLOATS   ((DIMK / 4) * BN * 4)       // 8192 per buffer
#define SMEM_BYTES  ((XS_FLOATS + 2 * CS_FLOATS) * 4)   // 81920

__device__ float g_cnorm[KCENT];

// ---- f32x2 helpers (exact fp32 semantics, 2 FMAs per instruction) ----
__device__ __forceinline__ void fma2(unsigned long long& d,
                                     unsigned long long a,
                                     unsigned long long b) {
    asm("fma.rn.f32x2 %0, %1, %2, %0;" : "+l"(d) : "l"(a), "l"(b));
}
__device__ __forceinline__ float2 unpack2(unsigned long long v) {
    float2 f;
    asm("mov.b64 {%0, %1}, %2;" : "=f"(f.x), "=f"(f.y) : "l"(v));
    return f;
}
// 16-byte shared load producing two f32x2 operand registers
__device__ __forceinline__ void lds128(unsigned addr,
                                       unsigned long long& lo,
                                       unsigned long long& hi) {
    asm volatile(
        "{\n\t"
        ".reg .b32 t0, t1, t2, t3;\n\t"
        "ld.shared.v4.b32 {t0, t1, t2, t3}, [%2];\n\t"
        "mov.b64 %0, {t0, t1};\n\t"
        "mov.b64 %1, {t2, t3};\n\t"
        "}"
        : "=l"(lo), "=l"(hi) : "r"(addr));
}
__device__ __forceinline__ void cp_async16(unsigned smem_addr, const void* gptr) {
    asm volatile("cp.async.cg.shared.global [%0], [%1], 16;"
                 :: "r"(smem_addr), "l"(gptr));
}
__device__ __forceinline__ void cp_commit() {
    asm volatile("cp.async.commit_group;");
}
__device__ __forceinline__ void cp_wait_all() {
    asm volatile("cp.async.wait_group 0;" ::: "memory");
}

// ---- center squared norms ----
__global__ void cnorm_kernel(const float* __restrict__ centers) {
    int n = blockIdx.x * blockDim.x + threadIdx.x;
    if (n < KCENT) {
        const float* c = centers + (size_t)n * DIMK;
        float s = 0.f;
        #pragma unroll
        for (int k = 0; k < DIMK; k++) s = fmaf(c[k], c[k], s);
        g_cnorm[n] = s;
    }
}

// ---- fused GEMM + argmin, cp.async double-buffered C tiles ----
// Xs: [m][k]            64 x 64 floats (16 KB); a-reads LDS.128 broadcast
// Cs: quad-interleaved  [k/4][n][4], two 32 KB buffers;
//     b-reads LDS.128, contiguous 512B/warp (4-phase, conflict-free)
__global__ __launch_bounds__(THREADS, 2)
void label_kernel(const float* __restrict__ inpt,
                  const float* __restrict__ centers,
                  float* __restrict__ out) {
    extern __shared__ __align__(16) float smem[];
    float* Xs = smem;                       // XS_FLOATS
    float* Cs0 = smem + XS_FLOATS;          // CS_FLOATS
    float* Cs1 = Cs0 + CS_FLOATS;           // CS_FLOATS

    const int tid = threadIdx.x;
    const int ty  = tid >> 5;
    const int tx  = tid & 31;
    const int m0  = blockIdx.x * BM;
    const int mbase = ty * TM;

    // cp.async C-tile prefetch: thread -> (n = tid/2, h = tid&1), 8 x 16B
    const int cn_row = tid >> 1;
    const int cn_h   = tid & 1;
    const float* csrc_base = centers + (size_t)cn_row * DIMK + cn_h * 32;

    // Prefetch tile 0 into Cs0 (overlaps the X-tile global loads below)
    {
        unsigned cs = (unsigned)__cvta_generic_to_shared(Cs0);
        #pragma unroll
        for (int i4 = 0; i4 < 8; i4++) {
            const int k = cn_h * 32 + i4 * 4;
            cp_async16(cs + (unsigned)(((k >> 2) * (BN * 4) + cn_row * 4) * 4),
                       csrc_base + i4 * 4);
        }
        cp_commit();
    }

    // Load X tile: rows m0..m0+63, cols 64..127 (second slice)
    {
        const int r  = tid >> 4;
        const int kg = tid & 15;
        #pragma unroll
        for (int rep = 0; rep < 4; rep++) {
            const int m = r + rep * 16;
            float4 v = *reinterpret_cast<const float4*>(
                inpt + (size_t)(m0 + m) * INROW + DIMK + kg * 4);
            *reinterpret_cast<float4*>(&Xs[m * DIMK + kg * 4]) = v;
        }
    }

    const unsigned xs_base = (unsigned)__cvta_generic_to_shared(Xs);
    const unsigned cs_base0 = (unsigned)__cvta_generic_to_shared(Cs0);
    const unsigned cs_base1 = (unsigned)__cvta_generic_to_shared(Cs1);

    float bestd[TM];
    int   bestn[TM];
    #pragma unroll
    for (int i = 0; i < TM; i++) {
        bestd[i] = __int_as_float(0x7f800000);
        bestn[i] = 0;
    }

    #pragma unroll 1
    for (int t = 0; t < KCENT / BN; t++) {
        const int n0 = t * BN;
        cp_wait_all();          // C tile t landed
        __syncthreads();        // ...visible to all warps; compute(t-1) done

        // Prefetch tile t+1 into the other buffer (overlaps compute of t)
        if (t + 1 < KCENT / BN) {
            unsigned cs_next = (t & 1) ? cs_base0 : cs_base1;
            const float* src = csrc_base + (size_t)(n0 + BN) * DIMK;
            #pragma unroll
            for (int i4 = 0; i4 < 8; i4++) {
                const int k = cn_h * 32 + i4 * 4;
                cp_async16(cs_next +
                           (unsigned)(((k >> 2) * (BN * 4) + cn_row * 4) * 4),
                           src + i4 * 4);
            }
            cp_commit();
        }

        const unsigned cs_cur = (t & 1) ? cs_base1 : cs_base0;

        // acc[i][j] packs (sum over even k, sum over odd k)
        unsigned long long acc[TM][TN];
        #pragma unroll
        for (int i = 0; i < TM; i++)
            #pragma unroll
            for (int j = 0; j < TN; j++) acc[i][j] = 0ull;

        #pragma unroll 4
        for (int kq = 0; kq < DIMK / 4; kq++) {   // 4 k-values per step
            unsigned long long b_lo[TN], b_hi[TN];
            #pragma unroll
            for (int j = 0; j < TN; j++)
                lds128(cs_cur +
                       (unsigned)((kq * (BN * 4) + (tx + 32 * j) * 4) * 4),
                       b_lo[j], b_hi[j]);
            unsigned long long a_lo[TM], a_hi[TM];
            #pragma unroll
            for (int i = 0; i < TM; i++)
                lds128(xs_base +
                       (unsigned)(((mbase + i) * DIMK + kq * 4) * 4),
                       a_lo[i], a_hi[i]);
            #pragma unroll
            for (int i = 0; i < TM; i++)
                #pragma unroll
                for (int j = 0; j < TN; j++) {
                    fma2(acc[i][j], a_lo[i], b_lo[j]);
                    fma2(acc[i][j], a_hi[i], b_hi[j]);
                }
        }

        // Epilogue: d = ||c||^2 - 2*dot, running argmin (ascending n ->
        // first-minimum semantics of jnp.argmin)
        float cn[TN];
        #pragma unroll
        for (int j = 0; j < TN; j++)
            cn[j] = __ldg(&g_cnorm[n0 + tx + 32 * j]);

        #pragma unroll
        for (int i = 0; i < TM; i++) {
            #pragma unroll
            for (int j = 0; j < TN; j++) {
                float2 s = unpack2(acc[i][j]);
                float d = fmaf(-2.0f, s.x, cn[j]);
                d = fmaf(-2.0f, s.y, d);
                int n = n0 + tx + 32 * j;
                if (d < bestd[i]) { bestd[i] = d; bestn[i] = n; }
            }
        }
    }

    // Warp reduction per row (lanes hold disjoint n-sets); tie -> lower index
    #pragma unroll
    for (int i = 0; i < TM; i++) {
        float d = bestd[i];
        int   n = bestn[i];
        #pragma unroll
        for (int off = 16; off > 0; off >>= 1) {
            float od = __shfl_down_sync(0xffffffffu, d, off);
            int   on = __shfl_down_sync(0xffffffffu, n, off);
            if (od < d || (od == d && on < n)) { d = od; n = on; }
        }
        // Output dtype is float32: labels 0..1023 exactly representable.
        if (tx == 0) out[m0 + mbase + i] = (float)n;
    }
}

extern "C" void kernel_launch(void* const* d_in, const int* in_sizes, int n_in,
                              void* d_out, int out_size) {
    // Identify inputs by element count (robust to metadata ordering):
    //   inpt: 16777216 elements (unique); centers1: second 65536-elem tensor
    const float* inpt     = nullptr;
    const float* centers1 = nullptr;
    int centers_seen = 0;
    for (int i = 0; i < n_in; i++) {
        if (in_sizes[i] == NPTS * INROW) {
            inpt = (const float*)d_in[i];
        } else if (in_sizes[i] == KCENT * DIMK) {
            centers_seen++;
            if (centers_seen == 2) centers1 = (const float*)d_in[i];
        }
    }
    if (!inpt)     inpt     = (const float*)d_in[0];
    if (!centers1) centers1 = (const float*)d_in[n_in - 1];

    float* out = (float*)d_out;

    // Host-side attribute set (idempotent; not a stream op -> capture-legal)
    cudaFuncSetAttribute(label_kernel,
                         cudaFuncAttributeMaxDynamicSharedMemorySize,
                         SMEM_BYTES);

    cnorm_kernel<<<(KCENT + 255) / 256, 256>>>(centers1);
    label_kernel<<<NPTS / BM, THREADS, SMEM_BYTES>>>(inpt, centers1, out);
}